// round 1
// baseline (speedup 1.0000x reference)
#include <cuda_runtime.h>
#include <cstdint>

#define NUM_AGENTS 8
#define DAG 64
#define IN_DIM 512
#define BATCH_N 65536

// Preprocessed weights (device globals: no allocations allowed).
// g_W1[e][d] = Wh[e][d] - Wc[e][d]/7         (row-major, e-major)
// g_W2T[d][e] = Wc[e][d]/7                   (transposed, d-major)
__device__ __align__(16) float g_W1[DAG * DAG];
__device__ __align__(16) float g_W2T[DAG * DAG];

__global__ void prep_kernel(const float* __restrict__ Wh,
                            const float* __restrict__ Wc) {
    int i = blockIdx.x * blockDim.x + threadIdx.x;  // 0..4095
    if (i < DAG * DAG) {
        int e = i >> 6;
        int d = i & 63;
        float c = Wc[i] * (1.0f / 7.0f);
        g_W1[i] = Wh[i] - c;
        g_W2T[d * DAG + e] = c;
    }
}

__device__ __forceinline__ void ffma2(unsigned long long& acc,
                                      unsigned long long a,
                                      unsigned long long b) {
    asm("fma.rn.f32x2 %0, %1, %2, %0;" : "+l"(acc) : "l"(a), "l"(b));
}
__device__ __forceinline__ float f2lo(unsigned long long v) {
    return __uint_as_float((unsigned)v);
}
__device__ __forceinline__ float f2hi(unsigned long long v) {
    return __uint_as_float((unsigned)(v >> 32));
}

// tanh(y) = (e^{2y}-1)/(e^{2y}+1); EX2 + RCP approx, ~1e-6 rel err.
__device__ __forceinline__ float tanh_fast(float y) {
    float e = __expf(y + y);
    return __fdividef(e - 1.0f, e + 1.0f);
}

__global__ void __launch_bounds__(256, 1)
comm_kernel(const float* __restrict__ x, float* __restrict__ out) {
    __shared__ float  xs[8][IN_DIM];     // per-warp row buffer, 16 KB
    __shared__ float2 ssd[8][DAG];       // per-warp duplicated s, 4 KB
    __shared__ float  w2s[DAG * DAG];    // W2^T [d][e], 16 KB

    const int tid  = threadIdx.x;
    const int warp = tid >> 5;
    const int lane = tid & 31;

    // Cooperative copy of W2^T into shared (coalesced float4).
    {
        const float4* src = (const float4*)g_W2T;
        float4*       dst = (float4*)w2s;
#pragma unroll
        for (int k = 0; k < 4; k++) dst[tid + 256 * k] = src[tid + 256 * k];
    }

    // Each lane caches W1 columns e0 = 2*lane, e1 = 2*lane+1 as packed
    // (d,d+1) f32x2 pairs: 2 x 32 u64 = 128 registers.
    unsigned long long w1a[32], w1b[32];
    {
        const ulonglong2* c0 = (const ulonglong2*)(g_W1 + (2 * lane) * DAG);
        const ulonglong2* c1 = (const ulonglong2*)(g_W1 + (2 * lane + 1) * DAG);
#pragma unroll
        for (int k = 0; k < 16; k++) {
            ulonglong2 v = c0[k];
            w1a[2 * k] = v.x; w1a[2 * k + 1] = v.y;
        }
#pragma unroll
        for (int k = 0; k < 16; k++) {
            ulonglong2 v = c1[k];
            w1b[2 * k] = v.x; w1b[2 * k + 1] = v.y;
        }
    }
    __syncthreads();  // w2s visible to all warps

    const int stride = gridDim.x * 8;
    int row = blockIdx.x * 8 + warp;
    if (row >= BATCH_N) return;

    const float4* xg  = (const float4*)x;
    float4*       xsw = (float4*)xs[warp];

    // Preload first row into registers.
    float4 r0 = xg[(size_t)row * 128 + lane];
    float4 r1 = xg[(size_t)row * 128 + lane + 32];
    float4 r2 = xg[(size_t)row * 128 + lane + 64];
    float4 r3 = xg[(size_t)row * 128 + lane + 96];

    while (true) {
        __syncwarp();
        xsw[lane]      = r0;
        xsw[lane + 32] = r1;
        xsw[lane + 64] = r2;
        xsw[lane + 96] = r3;
        __syncwarp();

        // Prefetch next row while we compute this one (latency hidden
        // behind ~700 FMA-pipe instructions).
        int next = row + stride;
        if (next < BATCH_N) {
            r0 = xg[(size_t)next * 128 + lane];
            r1 = xg[(size_t)next * 128 + lane + 32];
            r2 = xg[(size_t)next * 128 + lane + 64];
            r3 = xg[(size_t)next * 128 + lane + 96];
        }

        // s[d] = sum over agents; store duplicated (s,s) for packed t-loop.
        {
            float s0 = 0.f, s1 = 0.f;
#pragma unroll
            for (int a = 0; a < 8; a++) {
                s0 += xs[warp][a * 64 + lane];
                s1 += xs[warp][a * 64 + lane + 32];
            }
            ssd[warp][lane]      = make_float2(s0, s0);
            ssd[warp][lane + 32] = make_float2(s1, s1);
        }
        __syncwarp();

        // t[e] = sum_d s[d] * W2[e][d], packed over (e0,e1).
        unsigned long long tp = 0ull;
        {
            const ulonglong2* sp = (const ulonglong2*)ssd[warp];
#pragma unroll
            for (int dd = 0; dd < 32; dd++) {
                ulonglong2 sv = sp[dd];  // broadcast LDS.128
                unsigned long long wa =
                    *(const unsigned long long*)(w2s + (2 * dd) * DAG + 2 * lane);
                unsigned long long wb =
                    *(const unsigned long long*)(w2s + (2 * dd + 1) * DAG + 2 * lane);
                ffma2(tp, sv.x, wa);
                ffma2(tp, sv.y, wb);
            }
        }

        // Main term: acc[a][e] = sum_d xb[a][d] * W1[e][d], packed over d.
        unsigned long long acc0[8], acc1[8];
#pragma unroll
        for (int a = 0; a < 8; a++) { acc0[a] = 0ull; acc1[a] = 0ull; }
#pragma unroll
        for (int a = 0; a < 8; a++) {
            const ulonglong2* xa = (const ulonglong2*)(xs[warp] + a * 64);
#pragma unroll
            for (int k = 0; k < 16; k++) {
                ulonglong2 xv = xa[k];  // broadcast LDS.128 -> 2 packed d-pairs
                ffma2(acc0[a], xv.x, w1a[2 * k]);
                ffma2(acc1[a], xv.x, w1b[2 * k]);
                ffma2(acc0[a], xv.y, w1a[2 * k + 1]);
                ffma2(acc1[a], xv.y, w1b[2 * k + 1]);
            }
        }

        // Epilogue: horizontal sum + broadcast term + tanh + coalesced STG.64.
        {
            float t0 = f2lo(tp), t1 = f2hi(tp);
            float2* op = (float2*)(out + (size_t)row * IN_DIM + 2 * lane);
#pragma unroll
            for (int a = 0; a < 8; a++) {
                float y0 = f2lo(acc0[a]) + f2hi(acc0[a]) + t0;
                float y1 = f2lo(acc1[a]) + f2hi(acc1[a]) + t1;
                op[a * 32] = make_float2(tanh_fast(y0), tanh_fast(y1));
            }
        }

        row = next;
        if (row >= BATCH_N) break;
    }
}

extern "C" void kernel_launch(void* const* d_in, const int* in_sizes, int n_in,
                              void* d_out, int out_size) {
    const float* x  = (const float*)d_in[0];
    const float* Wh = (const float*)d_in[1];
    const float* Wc = (const float*)d_in[2];
    float* out = (float*)d_out;

    prep_kernel<<<16, 256>>>(Wh, Wc);
    comm_kernel<<<152, 256>>>(x, out);
}

// round 3
// speedup vs baseline: 1.7859x; 1.7859x over previous
#include <cuda_runtime.h>
#include <cuda_bf16.h>
#include <cstdint>

// out = tanh( Xa @ W1'^T + agent-sum(Xa @ W2^T) ), Xa: [524288, 64] fp32,
// W1' = Wh - Wc/7, W2 = Wc/7. Split-bf16 HMMA (mma.sync m16n8k16, fp32 acc):
// Y = xh*Wh + xl*Wh + xh*Wl. Tile: 32 agent rows x 64 e-cols per CTA iter.

#define NTILES 16384  // 524288 / 32

__device__ __align__(16) float g_W1[4096];  // (Wh - Wc/7)[e][d]
__device__ __align__(16) float g_W2[4096];  // (Wc/7)[e][d]

__global__ void prep_kernel(const float* __restrict__ Wh,
                            const float* __restrict__ Wc) {
    int i = blockIdx.x * blockDim.x + threadIdx.x;
    if (i < 4096) {
        float c = Wc[i] * (1.0f / 7.0f);
        g_W1[i] = Wh[i] - c;
        g_W2[i] = c;
    }
}

__device__ __forceinline__ uint32_t smem_u32(const void* p) {
    uint32_t a;
    asm("{ .reg .u64 t; cvta.to.shared.u64 t, %1; cvt.u32.u64 %0, t; }"
        : "=r"(a) : "l"(p));
    return a;
}

__device__ __forceinline__ uint32_t pack_bf16(float a, float b) {
    __nv_bfloat162 t = __float22bfloat162_rn(make_float2(a, b));
    return *reinterpret_cast<uint32_t*>(&t);
}

__device__ __forceinline__ void mma_bf16(float* c, const uint32_t* a,
                                         const uint32_t* b) {
    asm volatile(
        "mma.sync.aligned.m16n8k16.row.col.f32.bf16.bf16.f32 "
        "{%0,%1,%2,%3}, {%4,%5,%6,%7}, {%8,%9}, {%0,%1,%2,%3};"
        : "+f"(c[0]), "+f"(c[1]), "+f"(c[2]), "+f"(c[3])
        : "r"(a[0]), "r"(a[1]), "r"(a[2]), "r"(a[3]), "r"(b[0]), "r"(b[1]));
}

__device__ __forceinline__ void ldsm4(uint32_t* r, uint32_t addr) {
    asm volatile(
        "ldmatrix.sync.aligned.m8n8.x4.shared.b16 {%0,%1,%2,%3}, [%4];"
        : "=r"(r[0]), "=r"(r[1]), "=r"(r[2]), "=r"(r[3])
        : "r"(addr));
}

__device__ __forceinline__ float tanh_fast(float y) {
    float e = __expf(y + y);
    return __fdividef(e - 1.0f, e + 1.0f);
}

__global__ void __launch_bounds__(256)
comm_hmma(const float* __restrict__ x, float* __restrict__ out) {
    __shared__ __align__(16) char xs[8192];  // xh [0,4096), xl [4096,8192)

    const int tid = threadIdx.x;
    const int w = tid >> 5;
    const int lane = tid & 31;
    const int colbase = (w & 3) << 4;  // 16 e-cols per warp

    // ---- Build B fragments in registers (once). bf[mat][split][nb][ks][2] ----
    uint32_t bf[2][2][2][4][2];
#pragma unroll
    for (int mat = 0; mat < 2; mat++) {
        const float* W = mat ? g_W2 : g_W1;
#pragma unroll
        for (int nb = 0; nb < 2; nb++) {
            int n = colbase + (nb << 3) + (lane >> 2);
#pragma unroll
            for (int ks = 0; ks < 4; ks++) {
                int k0 = (ks << 4) + ((lane & 3) << 1);
                float w00 = W[n * 64 + k0],     w01 = W[n * 64 + k0 + 1];
                float w10 = W[n * 64 + k0 + 8], w11 = W[n * 64 + k0 + 9];
                float h00 = __bfloat162float(__float2bfloat16(w00));
                float h01 = __bfloat162float(__float2bfloat16(w01));
                float h10 = __bfloat162float(__float2bfloat16(w10));
                float h11 = __bfloat162float(__float2bfloat16(w11));
                bf[mat][0][nb][ks][0] = pack_bf16(h00, h01);
                bf[mat][0][nb][ks][1] = pack_bf16(h10, h11);
                bf[mat][1][nb][ks][0] = pack_bf16(w00 - h00, w01 - h01);
                bf[mat][1][nb][ks][1] = pack_bf16(w10 - h10, w11 - h11);
            }
        }
    }

    // ---- ldmatrix addressing (swizzled 128B rows, 16B chunks) ----
    const int lrow = ((w >> 2) << 4) + (lane & 7) + ((lane >> 3) & 1) * 8;
    const uint32_t xs_base = smem_u32(xs);
    const uint32_t ldsm_row = xs_base + lrow * 128;
    const int chunk_hi = (lane >> 4);  // 0 for lanes 0-15, 1 for 16-31

    // ---- STS addressing: thread t -> row t/8, chunk t%8 (swizzled) ----
    const int srow = tid >> 3, schunk = tid & 7;
    const uint32_t sts_off = srow * 128 + ((schunk ^ (srow & 7)) << 4);

    const float4* xg = (const float4*)x;
    const int grid = gridDim.x;
    int t = blockIdx.x;

    size_t gidx = (size_t)t * 512 + (size_t)(tid >> 3) * 16 + ((tid & 7) << 1);
    float4 v0 = xg[gidx], v1 = xg[gidx + 1];

    while (true) {
        __syncthreads();  // previous tile fully consumed
        // split-bf16 convert + STS
        {
            float h0 = __bfloat162float(__float2bfloat16(v0.x));
            float h1 = __bfloat162float(__float2bfloat16(v0.y));
            float h2 = __bfloat162float(__float2bfloat16(v0.z));
            float h3 = __bfloat162float(__float2bfloat16(v0.w));
            float h4 = __bfloat162float(__float2bfloat16(v1.x));
            float h5 = __bfloat162float(__float2bfloat16(v1.y));
            float h6 = __bfloat162float(__float2bfloat16(v1.z));
            float h7 = __bfloat162float(__float2bfloat16(v1.w));
            uint4 hv = make_uint4(pack_bf16(h0, h1), pack_bf16(h2, h3),
                                  pack_bf16(h4, h5), pack_bf16(h6, h7));
            uint4 lv = make_uint4(pack_bf16(v0.x - h0, v0.y - h1),
                                  pack_bf16(v0.z - h2, v0.w - h3),
                                  pack_bf16(v1.x - h4, v1.y - h5),
                                  pack_bf16(v1.z - h6, v1.w - h7));
            *(uint4*)(xs + sts_off) = hv;
            *(uint4*)(xs + 4096 + sts_off) = lv;
        }
        __syncthreads();

        int tn = t + grid;
        bool more = (tn < NTILES);
        if (more) {  // prefetch next tile behind the MMAs
            gidx = (size_t)tn * 512 + (size_t)(tid >> 3) * 16 + ((tid & 7) << 1);
            v0 = xg[gidx];
            v1 = xg[gidx + 1];
        }

        float acc[2][2][4] = {};
#pragma unroll
        for (int ks = 0; ks < 4; ks++) {
            uint32_t ca =
                ldsm_row + ((((ks << 1) + chunk_hi) ^ (lrow & 7)) << 4);
            uint32_t ah[4], al[4];
            ldsm4(ah, ca);
            // xh * Wh
            mma_bf16(acc[0][0], ah, bf[0][0][0][ks]);
            mma_bf16(acc[0][1], ah, bf[0][0][1][ks]);
            mma_bf16(acc[1][0], ah, bf[1][0][0][ks]);
            mma_bf16(acc[1][1], ah, bf[1][0][1][ks]);
            // xh * Wl
            mma_bf16(acc[0][0], ah, bf[0][1][0][ks]);
            mma_bf16(acc[0][1], ah, bf[0][1][1][ks]);
            mma_bf16(acc[1][0], ah, bf[1][1][0][ks]);
            mma_bf16(acc[1][1], ah, bf[1][1][1][ks]);
            // xl * Wh
            ldsm4(al, ca + 4096);
            mma_bf16(acc[0][0], al, bf[0][0][0][ks]);
            mma_bf16(acc[0][1], al, bf[0][0][1][ks]);
            mma_bf16(acc[1][0], al, bf[1][0][0][ks]);
            mma_bf16(acc[1][1], al, bf[1][0][1][ks]);
        }

        // ---- epilogue: agent-sum of W2 half via quad shuffles, tanh, STG ----
        {
            int R0 = t * 32 + ((w >> 2) << 4) + (lane >> 2);
            int R1 = R0 + 8;
#pragma unroll
            for (int nb = 0; nb < 2; nb++) {
                float s0 = acc[1][nb][0], s1 = acc[1][nb][1];
                float s2 = acc[1][nb][2], s3 = acc[1][nb][3];
#pragma unroll
                for (int m = 4; m <= 16; m <<= 1) {
                    s0 += __shfl_xor_sync(0xffffffffu, s0, m);
                    s1 += __shfl_xor_sync(0xffffffffu, s1, m);
                    s2 += __shfl_xor_sync(0xffffffffu, s2, m);
                    s3 += __shfl_xor_sync(0xffffffffu, s3, m);
                }
                float o0 = tanh_fast(acc[0][nb][0] + s0);
                float o1 = tanh_fast(acc[0][nb][1] + s1);
                float o2 = tanh_fast(acc[0][nb][2] + s2);
                float o3 = tanh_fast(acc[0][nb][3] + s3);
                int cc = colbase + (nb << 3) + ((lane & 3) << 1);
                *(float2*)(out + (size_t)R0 * 64 + cc) = make_float2(o0, o1);
                *(float2*)(out + (size_t)R1 * 64 + cc) = make_float2(o2, o3);
            }
        }

        if (!more) break;
        t = tn;
    }
}

extern "C" void kernel_launch(void* const* d_in, const int* in_sizes, int n_in,
                              void* d_out, int out_size) {
    const float* x  = (const float*)d_in[0];
    const float* Wh = (const float*)d_in[1];
    const float* Wc = (const float*)d_in[2];
    float* out = (float*)d_out;

    int dev = 0, sms = 148;
    cudaGetDevice(&dev);
    cudaDeviceGetAttribute(&sms, cudaDevAttrMultiProcessorCount, dev);

    prep_kernel<<<16, 256>>>(Wh, Wc);
    comm_hmma<<<2 * sms, 256>>>(x, out);
}